// round 3
// baseline (speedup 1.0000x reference)
#include <cuda_runtime.h>
#include <cstdint>

// ---------------- problem constants ----------------
#define Bsz   2
#define Lseq  4096
#define Mrows 8192          // B*L
#define DM    768
#define DI    1536
#define DS    16
#define DR    48
#define NL    4
#define XD    80            // DT_RANK + 2*D_STATE
#define CLK   64            // scan chunk length
#define NCH   64            // number of chunks (L / CLK)

// ---------------- scratch (device global; allocation-free) ----------------
#define OFF_H      0ull
#define OFF_RES    6291456ull
#define OFF_HN     12582912ull
#define OFF_XZ     18874368ull
#define OFF_XC     44040192ull
#define OFF_XDBL   56623104ull
#define OFF_DELTA  57278464ull
#define OFF_Y      69861376ull
#define OFF_PR     82444288ull
#define OFF_SA     85590016ull
#define BUF_TOTAL  88735744ull

static __device__ float g_buf[BUF_TOTAL];

// ---------------- embed: h[m,d] = sum_i x[b,i,l]*eW[d,i] + eb[d] ----------------
__global__ void embed_kernel(const float* __restrict__ x, const float* __restrict__ eW,
                             const float* __restrict__ eb, float* __restrict__ h)
{
    __shared__ float xs[64];
    int m = blockIdx.x;
    int b = m >> 12, l = m & 4095;
    int tid = threadIdx.x;
    if (tid < 64) xs[tid] = x[(size_t)(b * 64 + tid) * 4096 + l];
    __syncthreads();
#pragma unroll
    for (int t = 0; t < 3; t++) {
        int d = t * 256 + tid;
        float acc = eb[d];
        const float4* wr = (const float4*)(eW + (size_t)d * 64);
#pragma unroll
        for (int i = 0; i < 16; i++) {
            float4 w = wr[i];
            acc += w.x * xs[i * 4 + 0] + w.y * xs[i * 4 + 1]
                 + w.z * xs[i * 4 + 2] + w.w * xs[i * 4 + 3];
        }
        h[(size_t)m * DM + d] = acc;
    }
}

// ---------------- residual add + layernorm ----------------
__global__ void ln_kernel(const float* __restrict__ hin, float* __restrict__ res,
                          const float* __restrict__ w, const float* __restrict__ bia,
                          float* __restrict__ out, int addRes)
{
    __shared__ float red[8];
    int m = blockIdx.x, tid = threadIdx.x;
    size_t base = (size_t)m * DM;
    float v[3];
#pragma unroll
    for (int t = 0; t < 3; t++) {
        int idx = t * 256 + tid;
        float hv = hin[base + idx];
        if (addRes) hv += res[base + idx];
        res[base + idx] = hv;
        v[t] = hv;
    }
    float s = v[0] + v[1] + v[2];
#pragma unroll
    for (int o = 16; o > 0; o >>= 1) s += __shfl_xor_sync(0xffffffffu, s, o);
    if ((tid & 31) == 0) red[tid >> 5] = s;
    __syncthreads();
    float mean = (red[0] + red[1] + red[2] + red[3] + red[4] + red[5] + red[6] + red[7]) * (1.f / 768.f);
    float q = 0.f;
#pragma unroll
    for (int t = 0; t < 3; t++) { float dv = v[t] - mean; q += dv * dv; }
#pragma unroll
    for (int o = 16; o > 0; o >>= 1) q += __shfl_xor_sync(0xffffffffu, q, o);
    __syncthreads();                       // everyone done reading red
    if ((tid & 31) == 0) red[tid >> 5] = q;
    __syncthreads();
    float var = (red[0] + red[1] + red[2] + red[3] + red[4] + red[5] + red[6] + red[7]) * (1.f / 768.f);
    float rstd = rsqrtf(var + 1e-5f);
#pragma unroll
    for (int t = 0; t < 3; t++) {
        int idx = t * 256 + tid;
        out[base + idx] = (v[t] - mean) * rstd * w[idx] + bia[idx];
    }
}

// ---------------- generic TN GEMM: C[m,n] = sum_k A[m,k]*W[n,k]  (fp32 SIMT) ----------------
// Double-buffered SMEM: one __syncthreads per K-step, global prefetch overlaps compute.
// act: 0 = none, 1 = softplus(acc + bias[n])
__global__ __launch_bounds__(256) void gemm_tn(
    const float* __restrict__ A, int lda,
    const float* __restrict__ W, int ldw,
    float* __restrict__ C, int ldc,
    int N, int K,
    const float* __restrict__ bias, int act)
{
    __shared__ float As[2][16][128];
    __shared__ float Ws[2][16][128];
    const int tid = threadIdx.x;
    const int m0 = blockIdx.y * 128;
    const int n0 = blockIdx.x * 128;
    const int tx = tid & 15;
    const int ty = tid >> 4;
    const int ar = (tid * 2) >> 2;        // row in tile (0..127)
    const int ac = ((tid * 2) & 3) * 4;   // k offset (0 or 8)
    const bool wvalid = (n0 + ar < N);

    float acc[8][8];
#pragma unroll
    for (int i = 0; i < 8; i++)
#pragma unroll
        for (int j = 0; j < 8; j++) acc[i][j] = 0.f;

    // ---- initial tile load (k0 = 0) into buffer 0 ----
    {
        const float* Ap = A + (size_t)(m0 + ar) * lda + ac;
        float4 a0 = *(const float4*)Ap;
        float4 a1 = *(const float4*)(Ap + 4);
        float4 w0 = make_float4(0.f, 0.f, 0.f, 0.f), w1 = w0;
        if (wvalid) {
            const float* Wp = W + (size_t)(n0 + ar) * ldw + ac;
            w0 = *(const float4*)Wp;
            w1 = *(const float4*)(Wp + 4);
        }
        As[0][ac + 0][ar] = a0.x; As[0][ac + 1][ar] = a0.y; As[0][ac + 2][ar] = a0.z; As[0][ac + 3][ar] = a0.w;
        As[0][ac + 4][ar] = a1.x; As[0][ac + 5][ar] = a1.y; As[0][ac + 6][ar] = a1.z; As[0][ac + 7][ar] = a1.w;
        Ws[0][ac + 0][ar] = w0.x; Ws[0][ac + 1][ar] = w0.y; Ws[0][ac + 2][ar] = w0.z; Ws[0][ac + 3][ar] = w0.w;
        Ws[0][ac + 4][ar] = w1.x; Ws[0][ac + 5][ar] = w1.y; Ws[0][ac + 6][ar] = w1.z; Ws[0][ac + 7][ar] = w1.w;
    }
    __syncthreads();

    int buf = 0;
    for (int k0 = 0; k0 < K; k0 += 16) {
        const bool has_next = (k0 + 16) < K;
        float4 na0, na1, nw0, nw1;
        if (has_next) {
            const float* Ap = A + (size_t)(m0 + ar) * lda + (k0 + 16) + ac;
            na0 = *(const float4*)Ap;
            na1 = *(const float4*)(Ap + 4);
            nw0 = make_float4(0.f, 0.f, 0.f, 0.f); nw1 = nw0;
            if (wvalid) {
                const float* Wp = W + (size_t)(n0 + ar) * ldw + (k0 + 16) + ac;
                nw0 = *(const float4*)Wp;
                nw1 = *(const float4*)(Wp + 4);
            }
        }

        // compute on current buffer (gmem loads above are in flight)
#pragma unroll
        for (int kk = 0; kk < 16; kk++) {
            float4 af0 = *(const float4*)&As[buf][kk][ty * 8];
            float4 af1 = *(const float4*)&As[buf][kk][ty * 8 + 4];
            float4 wf0 = *(const float4*)&Ws[buf][kk][tx * 8];
            float4 wf1 = *(const float4*)&Ws[buf][kk][tx * 8 + 4];
            float am[8] = {af0.x, af0.y, af0.z, af0.w, af1.x, af1.y, af1.z, af1.w};
            float wn[8] = {wf0.x, wf0.y, wf0.z, wf0.w, wf1.x, wf1.y, wf1.z, wf1.w};
#pragma unroll
            for (int i = 0; i < 8; i++)
#pragma unroll
                for (int j = 0; j < 8; j++) acc[i][j] += am[i] * wn[j];
        }

        if (has_next) {
            int nb = buf ^ 1;
            As[nb][ac + 0][ar] = na0.x; As[nb][ac + 1][ar] = na0.y; As[nb][ac + 2][ar] = na0.z; As[nb][ac + 3][ar] = na0.w;
            As[nb][ac + 4][ar] = na1.x; As[nb][ac + 5][ar] = na1.y; As[nb][ac + 6][ar] = na1.z; As[nb][ac + 7][ar] = na1.w;
            Ws[nb][ac + 0][ar] = nw0.x; Ws[nb][ac + 1][ar] = nw0.y; Ws[nb][ac + 2][ar] = nw0.z; Ws[nb][ac + 3][ar] = nw0.w;
            Ws[nb][ac + 4][ar] = nw1.x; Ws[nb][ac + 5][ar] = nw1.y; Ws[nb][ac + 6][ar] = nw1.z; Ws[nb][ac + 7][ar] = nw1.w;
            __syncthreads();
            buf = nb;
        }
    }

#pragma unroll
    for (int i = 0; i < 8; i++) {
        int m = m0 + ty * 8 + i;
#pragma unroll
        for (int j = 0; j < 8; j++) {
            int n = n0 + tx * 8 + j;
            if (n < N) {
                float v = acc[i][j];
                if (act == 1) {
                    v += bias[n];
                    v = (v > 15.f) ? v : log1pf(__expf(v));
                }
                C[(size_t)m * ldc + n] = v;
            }
        }
    }
}

// ---------------- depthwise causal conv1d (k=4) + SiLU ----------------
__global__ void conv_kernel(const float* __restrict__ xz, const float* __restrict__ cw,
                            const float* __restrict__ cb, float* __restrict__ xc)
{
    int d = blockIdx.x * 256 + threadIdx.x;   // 0..1535
    int m = blockIdx.y;
    int l = m & 4095;
    float4 w4 = *(const float4*)(cw + (size_t)d * 4);   // w[0..3]
    float acc = cb[d];
    const float* p = xz + (size_t)m * (2 * DI) + d;
    acc += w4.w * p[0];
    if (l >= 1) acc += w4.z * p[-(2 * DI)];
    if (l >= 2) acc += w4.y * p[-2 * (2 * DI)];
    if (l >= 3) acc += w4.x * p[-3 * (2 * DI)];
    float sg = 1.f / (1.f + __expf(-acc));
    xc[(size_t)m * DI + d] = acc * sg;
}

// ---------------- scan phase 1: per-chunk prodA + partial state ----------------
__global__ void scan1_kernel(const float* __restrict__ delta, const float* __restrict__ xc,
                             const float* __restrict__ xdbl, const float* __restrict__ Alog,
                             float* __restrict__ pr, float* __restrict__ sa)
{
    __shared__ float Bsh[CLK][DS];
    int b = blockIdx.z, c = blockIdx.y;
    int d = blockIdx.x * 256 + threadIdx.x;
    int l0 = c * CLK;
    {
        int l = threadIdx.x >> 2, q = threadIdx.x & 3;
        float4 v = *(const float4*)(xdbl + (size_t)(b * Lseq + l0 + l) * XD + 48 + q * 4);
        Bsh[l][q * 4 + 0] = v.x; Bsh[l][q * 4 + 1] = v.y;
        Bsh[l][q * 4 + 2] = v.z; Bsh[l][q * 4 + 3] = v.w;
    }
    __syncthreads();
    float Ar[DS];
#pragma unroll
    for (int n = 0; n < DS; n++) Ar[n] = -__expf(Alog[(size_t)d * DS + n]);
    float s[DS], p[DS];
#pragma unroll
    for (int n = 0; n < DS; n++) { s[n] = 0.f; p[n] = 1.f; }
    int mbase = b * Lseq + l0;
    for (int l = 0; l < CLK; l++) {
        size_t off = (size_t)(mbase + l) * DI + d;
        float dl = delta[off], u = xc[off];
        float du = dl * u;
#pragma unroll
        for (int n = 0; n < DS; n++) {
            float e = __expf(dl * Ar[n]);
            p[n] *= e;
            s[n] = e * s[n] + du * Bsh[l][n];
        }
    }
    size_t base = ((size_t)(b * NCH + c) * DI + d) * DS;
#pragma unroll
    for (int n = 0; n < DS; n++) { pr[base + n] = p[n]; sa[base + n] = s[n]; }
}

// ---------------- scan phase 2: prefix over chunks; leaves init-state in sa ----------------
__global__ void scan2_kernel(const float* __restrict__ pr, float* __restrict__ sa)
{
    int gid = blockIdx.x * 256 + threadIdx.x;     // 0 .. B*DI*DS-1
    int b = gid / (DI * DS);
    int r = gid - b * (DI * DS);
    float s = 0.f;
    for (int c = 0; c < NCH; c++) {
        size_t idx = (size_t)(b * NCH + c) * (DI * DS) + r;
        float P = pr[idx], Sv = sa[idx];
        sa[idx] = s;            // exclusive prefix = init state for chunk c
        s = P * s + Sv;
    }
}

// ---------------- scan phase 3: replay with init state, fuse D-skip + SiLU gate ----------------
__global__ void scan3_kernel(const float* __restrict__ delta, const float* __restrict__ xc,
                             const float* __restrict__ xdbl, const float* __restrict__ Alog,
                             const float* __restrict__ Dv, const float* __restrict__ xz,
                             const float* __restrict__ sa, float* __restrict__ y)
{
    __shared__ float Bsh[CLK][DS];
    __shared__ float Csh[CLK][DS];
    int b = blockIdx.z, c = blockIdx.y;
    int d = blockIdx.x * 256 + threadIdx.x;
    int l0 = c * CLK;
    {
        int l = threadIdx.x >> 2, q = threadIdx.x & 3;
        const float* row = xdbl + (size_t)(b * Lseq + l0 + l) * XD;
        float4 v = *(const float4*)(row + 48 + q * 4);
        float4 u = *(const float4*)(row + 64 + q * 4);
        Bsh[l][q * 4 + 0] = v.x; Bsh[l][q * 4 + 1] = v.y;
        Bsh[l][q * 4 + 2] = v.z; Bsh[l][q * 4 + 3] = v.w;
        Csh[l][q * 4 + 0] = u.x; Csh[l][q * 4 + 1] = u.y;
        Csh[l][q * 4 + 2] = u.z; Csh[l][q * 4 + 3] = u.w;
    }
    __syncthreads();
    float Ar[DS];
#pragma unroll
    for (int n = 0; n < DS; n++) Ar[n] = -__expf(Alog[(size_t)d * DS + n]);
    float s[DS];
    size_t sbase = ((size_t)(b * NCH + c) * DI + d) * DS;
#pragma unroll
    for (int n = 0; n < DS; n++) s[n] = sa[sbase + n];
    float Dval = Dv[d];
    int mbase = b * Lseq + l0;
    for (int l = 0; l < CLK; l++) {
        size_t off = (size_t)(mbase + l) * DI + d;
        float dl = delta[off], u = xc[off];
        float du = dl * u;
        float accv = 0.f;
#pragma unroll
        for (int n = 0; n < DS; n++) {
            float e = __expf(dl * Ar[n]);
            s[n] = e * s[n] + du * Bsh[l][n];
            accv += s[n] * Csh[l][n];
        }
        float z = xz[(size_t)(mbase + l) * (2 * DI) + DI + d];
        float sg = 1.f / (1.f + __expf(-z));
        y[off] = (accv + Dval * u) * (z * sg);
    }
}

// ---------------- launch ----------------
extern "C" void kernel_launch(void* const* d_in, const int* in_sizes, int n_in,
                              void* d_out, int out_size)
{
    (void)in_sizes; (void)n_in; (void)out_size;
    const float* x    = (const float*)d_in[0];
    const float* eW   = (const float*)d_in[1];
    const float* eb   = (const float*)d_in[2];
    const float* nw   = (const float*)d_in[3];
    const float* nb   = (const float*)d_in[4];
    const float* inW  = (const float*)d_in[5];
    const float* cw   = (const float*)d_in[6];
    const float* cb   = (const float*)d_in[7];
    const float* xpW  = (const float*)d_in[8];
    const float* dtW  = (const float*)d_in[9];
    const float* dtb  = (const float*)d_in[10];
    const float* Alog = (const float*)d_in[11];
    const float* Dvec = (const float*)d_in[12];
    const float* outW = (const float*)d_in[13];
    const float* nfw  = (const float*)d_in[14];
    const float* nfb  = (const float*)d_in[15];
    float* outp = (float*)d_out;

    float* buf = nullptr;
    cudaGetSymbolAddress((void**)&buf, g_buf);
    float* h     = buf + OFF_H;
    float* res   = buf + OFF_RES;
    float* hn    = buf + OFF_HN;
    float* xz    = buf + OFF_XZ;
    float* xc    = buf + OFF_XC;
    float* xdbl  = buf + OFF_XDBL;
    float* dlt   = buf + OFF_DELTA;
    float* yb    = buf + OFF_Y;
    float* prb   = buf + OFF_PR;
    float* sab   = buf + OFF_SA;

    embed_kernel<<<Mrows, 256>>>(x, eW, eb, h);

    for (int i = 0; i < NL; i++) {
        ln_kernel<<<Mrows, 256>>>(h, res, nw + (size_t)i * DM, nb + (size_t)i * DM, hn, i == 0 ? 0 : 1);

        // in_proj: [8192,768] x [3072,768]^T -> xz [8192,3072]
        gemm_tn<<<dim3(24, 64), 256>>>(hn, DM, inW + (size_t)i * 2 * DI * DM, DM,
                                       xz, 2 * DI, 2 * DI, DM, nullptr, 0);

        conv_kernel<<<dim3(6, Mrows), 256>>>(xz, cw + (size_t)i * DI * 4, cb + (size_t)i * DI, xc);

        // x_proj: [8192,1536] x [80,1536]^T -> xdbl [8192,80]
        gemm_tn<<<dim3(1, 64), 256>>>(xc, DI, xpW + (size_t)i * XD * DI, DI,
                                      xdbl, XD, XD, DI, nullptr, 0);

        // dt_proj + softplus: [8192,48] x [1536,48]^T -> delta [8192,1536]
        gemm_tn<<<dim3(12, 64), 256>>>(xdbl, XD, dtW + (size_t)i * DI * DR, DR,
                                       dlt, DI, DI, DR, dtb + (size_t)i * DI, 1);

        scan1_kernel<<<dim3(6, NCH, Bsz), 256>>>(dlt, xc, xdbl, Alog + (size_t)i * DI * DS, prb, sab);
        scan2_kernel<<<192, 256>>>(prb, sab);
        scan3_kernel<<<dim3(6, NCH, Bsz), 256>>>(dlt, xc, xdbl, Alog + (size_t)i * DI * DS,
                                                 Dvec + (size_t)i * DI, xz, sab, yb);

        // out_proj: [8192,1536] x [768,1536]^T -> h [8192,768]
        gemm_tn<<<dim3(6, 64), 256>>>(yb, DI, outW + (size_t)i * DM * DI, DI,
                                      h, DM, DM, DI, nullptr, 0);
    }

    ln_kernel<<<Mrows, 256>>>(h, res, nfw, nfb, outp, 1);
}

// round 8
// speedup vs baseline: 1.4332x; 1.4332x over previous
#include <cuda_runtime.h>
#include <cuda_bf16.h>
#include <cstdint>

// ---------------- problem constants ----------------
#define Bsz   2
#define Lseq  4096
#define Mrows 8192          // B*L
#define DM    768
#define DI    1536
#define DS    16
#define DR    48
#define NL    4
#define XD    80            // DT_RANK + 2*D_STATE
#define CLK   64            // scan chunk length
#define NCH   64            // number of chunks (L / CLK)

// ---------------- scratch (device global; allocation-free) ----------------
#define OFF_H      0ull
#define OFF_RES    6291456ull
#define OFF_HN     12582912ull
#define OFF_XZ     18874368ull
#define OFF_XC     44040192ull
#define OFF_XDBL   56623104ull
#define OFF_DELTA  57278464ull
#define OFF_Y      69861376ull
#define OFF_PR     82444288ull
#define OFF_SA     85590016ull
#define BUF_TOTAL  88735744ull

static __device__ float g_buf[BUF_TOTAL];

// ---------------- embed ----------------
__global__ void embed_kernel(const float* __restrict__ x, const float* __restrict__ eW,
                             const float* __restrict__ eb, float* __restrict__ h)
{
    __shared__ float xs[64];
    int m = blockIdx.x;
    int b = m >> 12, l = m & 4095;
    int tid = threadIdx.x;
    if (tid < 64) xs[tid] = x[(size_t)(b * 64 + tid) * 4096 + l];
    __syncthreads();
#pragma unroll
    for (int t = 0; t < 3; t++) {
        int d = t * 256 + tid;
        float acc = eb[d];
        const float4* wr = (const float4*)(eW + (size_t)d * 64);
#pragma unroll
        for (int i = 0; i < 16; i++) {
            float4 w = wr[i];
            acc += w.x * xs[i * 4 + 0] + w.y * xs[i * 4 + 1]
                 + w.z * xs[i * 4 + 2] + w.w * xs[i * 4 + 3];
        }
        h[(size_t)m * DM + d] = acc;
    }
}

// ---------------- residual add + layernorm ----------------
__global__ void ln_kernel(const float* __restrict__ hin, float* __restrict__ res,
                          const float* __restrict__ w, const float* __restrict__ bia,
                          float* __restrict__ out, int addRes)
{
    __shared__ float red[8];
    int m = blockIdx.x, tid = threadIdx.x;
    size_t base = (size_t)m * DM;
    float v[3];
#pragma unroll
    for (int t = 0; t < 3; t++) {
        int idx = t * 256 + tid;
        float hv = hin[base + idx];
        if (addRes) hv += res[base + idx];
        res[base + idx] = hv;
        v[t] = hv;
    }
    float s = v[0] + v[1] + v[2];
#pragma unroll
    for (int o = 16; o > 0; o >>= 1) s += __shfl_xor_sync(0xffffffffu, s, o);
    if ((tid & 31) == 0) red[tid >> 5] = s;
    __syncthreads();
    float mean = (red[0] + red[1] + red[2] + red[3] + red[4] + red[5] + red[6] + red[7]) * (1.f / 768.f);
    float q = 0.f;
#pragma unroll
    for (int t = 0; t < 3; t++) { float dv = v[t] - mean; q += dv * dv; }
#pragma unroll
    for (int o = 16; o > 0; o >>= 1) q += __shfl_xor_sync(0xffffffffu, q, o);
    __syncthreads();
    if ((tid & 31) == 0) red[tid >> 5] = q;
    __syncthreads();
    float var = (red[0] + red[1] + red[2] + red[3] + red[4] + red[5] + red[6] + red[7]) * (1.f / 768.f);
    float rstd = rsqrtf(var + 1e-5f);
#pragma unroll
    for (int t = 0; t < 3; t++) {
        int idx = t * 256 + tid;
        out[base + idx] = (v[t] - mean) * rstd * w[idx] + bia[idx];
    }
}

// ============ tensor-core TN GEMM (3xBF16 split, fp32-equivalent) ============
// C[m,n] = sum_k A[m,k] * W[n,k].  Requires: M%128==0 (grid.y), N%128==0 (grid.x),
// K%32==0. No tail handling — only used for in_proj / out_proj.
#define BKP 40   // padded k-stride in bf16 elems (conflict-free: 20 banks/row)

__device__ __forceinline__ void mma16816(float c[4], const uint32_t a[4], const uint32_t b[2])
{
    asm volatile(
        "mma.sync.aligned.m16n8k16.row.col.f32.bf16.bf16.f32 "
        "{%0,%1,%2,%3}, {%4,%5,%6,%7}, {%8,%9}, {%0,%1,%2,%3};\n"
        : "+f"(c[0]), "+f"(c[1]), "+f"(c[2]), "+f"(c[3])
        : "r"(a[0]), "r"(a[1]), "r"(a[2]), "r"(a[3]), "r"(b[0]), "r"(b[1]));
}

__global__ __launch_bounds__(256) void gemm_tn_tc(
    const float* __restrict__ A, int lda,
    const float* __restrict__ W, int ldw,
    float* __restrict__ C, int ldc, int K)
{
    __shared__ __nv_bfloat16 Ah[128 * BKP], Al[128 * BKP];
    __shared__ __nv_bfloat16 Bh[128 * BKP], Bl[128 * BKP];

    const int tid  = threadIdx.x;
    const int m0   = blockIdx.y * 128;
    const int n0   = blockIdx.x * 128;
    const int lrow = tid >> 1;            // 0..127 (load row)
    const int kb   = (tid & 1) * 16;      // k sub-offset 0 or 16
    const int w    = tid >> 5;
    const int lane = tid & 31;
    const int wm   = (w >> 2) * 64;       // warp m offset (0 / 64)
    const int wn   = (w & 3) * 32;        // warp n offset (0/32/64/96)
    const int g    = lane >> 2;           // group id 0..7
    const int t    = lane & 3;            // thread-in-group

    float acc[4][4][4];
#pragma unroll
    for (int i = 0; i < 4; i++)
#pragma unroll
        for (int j = 0; j < 4; j++)
#pragma unroll
            for (int r = 0; r < 4; r++) acc[i][j][r] = 0.f;

    const float* Ap = A + (size_t)(m0 + lrow) * lda + kb;
    const float* Wp = W + (size_t)(n0 + lrow) * ldw + kb;

    float4 ra[4], rb[4];
#pragma unroll
    for (int i = 0; i < 4; i++) {
        ra[i] = *(const float4*)(Ap + i * 4);
        rb[i] = *(const float4*)(Wp + i * 4);
    }

    for (int k0 = 0; k0 < K; k0 += 32) {
        // ---- convert fp32 -> (hi, lo) bf16 and stage to SMEM ----
#pragma unroll
        for (int i = 0; i < 4; i++) {
            float va[4] = {ra[i].x, ra[i].y, ra[i].z, ra[i].w};
            float vb[4] = {rb[i].x, rb[i].y, rb[i].z, rb[i].w};
#pragma unroll
            for (int j = 0; j < 2; j++) {
                int idx = lrow * BKP + kb + i * 4 + 2 * j;
                __nv_bfloat162 h2, l2;
                __nv_bfloat16 h0 = __float2bfloat16(va[2 * j]);
                __nv_bfloat16 h1 = __float2bfloat16(va[2 * j + 1]);
                h2.x = h0; h2.y = h1;
                l2.x = __float2bfloat16(va[2 * j]     - __bfloat162float(h0));
                l2.y = __float2bfloat16(va[2 * j + 1] - __bfloat162float(h1));
                *(__nv_bfloat162*)&Ah[idx] = h2;
                *(__nv_bfloat162*)&Al[idx] = l2;
                __nv_bfloat16 g0 = __float2bfloat16(vb[2 * j]);
                __nv_bfloat16 g1 = __float2bfloat16(vb[2 * j + 1]);
                h2.x = g0; h2.y = g1;
                l2.x = __float2bfloat16(vb[2 * j]     - __bfloat162float(g0));
                l2.y = __float2bfloat16(vb[2 * j + 1] - __bfloat162float(g1));
                *(__nv_bfloat162*)&Bh[idx] = h2;
                *(__nv_bfloat162*)&Bl[idx] = l2;
            }
        }
        __syncthreads();

        // ---- prefetch next tile (LDG overlaps MMA below) ----
        if (k0 + 32 < K) {
            Ap += 32; Wp += 32;
#pragma unroll
            for (int i = 0; i < 4; i++) {
                ra[i] = *(const float4*)(Ap + i * 4);
                rb[i] = *(const float4*)(Wp + i * 4);
            }
        }

        // ---- two k16 substeps of MMAs ----
#pragma unroll
        for (int s = 0; s < 2; s++) {
            const int ks = s * 16;
            uint32_t ah[4][4], al_[4][4], bh[4][2], bl[4][2];
#pragma unroll
            for (int mt = 0; mt < 4; mt++) {
                int r0 = (wm + mt * 16 + g) * BKP + ks + 2 * t;
                int r1 = (wm + mt * 16 + g + 8) * BKP + ks + 2 * t;
                ah[mt][0] = *(const uint32_t*)&Ah[r0];
                ah[mt][1] = *(const uint32_t*)&Ah[r1];
                ah[mt][2] = *(const uint32_t*)&Ah[r0 + 8];
                ah[mt][3] = *(const uint32_t*)&Ah[r1 + 8];
                al_[mt][0] = *(const uint32_t*)&Al[r0];
                al_[mt][1] = *(const uint32_t*)&Al[r1];
                al_[mt][2] = *(const uint32_t*)&Al[r0 + 8];
                al_[mt][3] = *(const uint32_t*)&Al[r1 + 8];
            }
#pragma unroll
            for (int nt = 0; nt < 4; nt++) {
                int c0 = (wn + nt * 8 + g) * BKP + ks + 2 * t;
                bh[nt][0] = *(const uint32_t*)&Bh[c0];
                bh[nt][1] = *(const uint32_t*)&Bh[c0 + 8];
                bl[nt][0] = *(const uint32_t*)&Bl[c0];
                bl[nt][1] = *(const uint32_t*)&Bl[c0 + 8];
            }
#pragma unroll
            for (int mt = 0; mt < 4; mt++)
#pragma unroll
                for (int nt = 0; nt < 4; nt++) {
                    mma16816(acc[mt][nt], ah[mt],  bh[nt]);
                    mma16816(acc[mt][nt], ah[mt],  bl[nt]);
                    mma16816(acc[mt][nt], al_[mt], bh[nt]);
                }
        }
        __syncthreads();
    }

    // ---- epilogue ----
#pragma unroll
    for (int mt = 0; mt < 4; mt++) {
        int row = m0 + wm + mt * 16 + g;
#pragma unroll
        for (int nt = 0; nt < 4; nt++) {
            int col = n0 + wn + nt * 8 + 2 * t;
            float2 v0 = make_float2(acc[mt][nt][0], acc[mt][nt][1]);
            float2 v1 = make_float2(acc[mt][nt][2], acc[mt][nt][3]);
            *(float2*)&C[(size_t)row * ldc + col]       = v0;
            *(float2*)&C[(size_t)(row + 8) * ldc + col] = v1;
        }
    }
}

// ---------------- fp32 SIMT GEMM (kept for x_proj / dt_proj odd shapes) ----------------
__global__ __launch_bounds__(256) void gemm_tn(
    const float* __restrict__ A, int lda,
    const float* __restrict__ W, int ldw,
    float* __restrict__ C, int ldc,
    int N, int K,
    const float* __restrict__ bias, int act)
{
    __shared__ float As[2][16][128];
    __shared__ float Ws[2][16][128];
    const int tid = threadIdx.x;
    const int m0 = blockIdx.y * 128;
    const int n0 = blockIdx.x * 128;
    const int tx = tid & 15;
    const int ty = tid >> 4;
    const int ar = (tid * 2) >> 2;
    const int ac = ((tid * 2) & 3) * 4;
    const bool wvalid = (n0 + ar < N);

    float acc[8][8];
#pragma unroll
    for (int i = 0; i < 8; i++)
#pragma unroll
        for (int j = 0; j < 8; j++) acc[i][j] = 0.f;

    {
        const float* Ap = A + (size_t)(m0 + ar) * lda + ac;
        float4 a0 = *(const float4*)Ap;
        float4 a1 = *(const float4*)(Ap + 4);
        float4 w0 = make_float4(0.f, 0.f, 0.f, 0.f), w1 = w0;
        if (wvalid) {
            const float* Wp = W + (size_t)(n0 + ar) * ldw + ac;
            w0 = *(const float4*)Wp;
            w1 = *(const float4*)(Wp + 4);
        }
        As[0][ac + 0][ar] = a0.x; As[0][ac + 1][ar] = a0.y; As[0][ac + 2][ar] = a0.z; As[0][ac + 3][ar] = a0.w;
        As[0][ac + 4][ar] = a1.x; As[0][ac + 5][ar] = a1.y; As[0][ac + 6][ar] = a1.z; As[0][ac + 7][ar] = a1.w;
        Ws[0][ac + 0][ar] = w0.x; Ws[0][ac + 1][ar] = w0.y; Ws[0][ac + 2][ar] = w0.z; Ws[0][ac + 3][ar] = w0.w;
        Ws[0][ac + 4][ar] = w1.x; Ws[0][ac + 5][ar] = w1.y; Ws[0][ac + 6][ar] = w1.z; Ws[0][ac + 7][ar] = w1.w;
    }
    __syncthreads();

    int buf = 0;
    for (int k0 = 0; k0 < K; k0 += 16) {
        const bool has_next = (k0 + 16) < K;
        float4 na0, na1, nw0, nw1;
        if (has_next) {
            const float* Ap = A + (size_t)(m0 + ar) * lda + (k0 + 16) + ac;
            na0 = *(const float4*)Ap;
            na1 = *(const float4*)(Ap + 4);
            nw0 = make_float4(0.f, 0.f, 0.f, 0.f); nw1 = nw0;
            if (wvalid) {
                const float* Wp = W + (size_t)(n0 + ar) * ldw + (k0 + 16) + ac;
                nw0 = *(const float4*)Wp;
                nw1 = *(const float4*)(Wp + 4);
            }
        }
#pragma unroll
        for (int kk = 0; kk < 16; kk++) {
            float4 af0 = *(const float4*)&As[buf][kk][ty * 8];
            float4 af1 = *(const float4*)&As[buf][kk][ty * 8 + 4];
            float4 wf0 = *(const float4*)&Ws[buf][kk][tx * 8];
            float4 wf1 = *(const float4*)&Ws[buf][kk][tx * 8 + 4];
            float am[8] = {af0.x, af0.y, af0.z, af0.w, af1.x, af1.y, af1.z, af1.w};
            float wn[8] = {wf0.x, wf0.y, wf0.z, wf0.w, wf1.x, wf1.y, wf1.z, wf1.w};
#pragma unroll
            for (int i = 0; i < 8; i++)
#pragma unroll
                for (int j = 0; j < 8; j++) acc[i][j] += am[i] * wn[j];
        }
        if (has_next) {
            int nb = buf ^ 1;
            As[nb][ac + 0][ar] = na0.x; As[nb][ac + 1][ar] = na0.y; As[nb][ac + 2][ar] = na0.z; As[nb][ac + 3][ar] = na0.w;
            As[nb][ac + 4][ar] = na1.x; As[nb][ac + 5][ar] = na1.y; As[nb][ac + 6][ar] = na1.z; As[nb][ac + 7][ar] = na1.w;
            Ws[nb][ac + 0][ar] = nw0.x; Ws[nb][ac + 1][ar] = nw0.y; Ws[nb][ac + 2][ar] = nw0.z; Ws[nb][ac + 3][ar] = nw0.w;
            Ws[nb][ac + 4][ar] = nw1.x; Ws[nb][ac + 5][ar] = nw1.y; Ws[nb][ac + 6][ar] = nw1.z; Ws[nb][ac + 7][ar] = nw1.w;
            __syncthreads();
            buf = nb;
        }
    }

#pragma unroll
    for (int i = 0; i < 8; i++) {
        int m = m0 + ty * 8 + i;
#pragma unroll
        for (int j = 0; j < 8; j++) {
            int n = n0 + tx * 8 + j;
            if (n < N) {
                float v = acc[i][j];
                if (act == 1) {
                    v += bias[n];
                    v = (v > 15.f) ? v : log1pf(__expf(v));
                }
                C[(size_t)m * ldc + n] = v;
            }
        }
    }
}

// ---------------- depthwise causal conv1d (k=4) + SiLU ----------------
__global__ void conv_kernel(const float* __restrict__ xz, const float* __restrict__ cw,
                            const float* __restrict__ cb, float* __restrict__ xc)
{
    int d = blockIdx.x * 256 + threadIdx.x;
    int m = blockIdx.y;
    int l = m & 4095;
    float4 w4 = *(const float4*)(cw + (size_t)d * 4);
    float acc = cb[d];
    const float* p = xz + (size_t)m * (2 * DI) + d;
    acc += w4.w * p[0];
    if (l >= 1) acc += w4.z * p[-(2 * DI)];
    if (l >= 2) acc += w4.y * p[-2 * (2 * DI)];
    if (l >= 3) acc += w4.x * p[-3 * (2 * DI)];
    float sg = 1.f / (1.f + __expf(-acc));
    xc[(size_t)m * DI + d] = acc * sg;
}

// ---------------- scan phase 1 ----------------
__global__ void scan1_kernel(const float* __restrict__ delta, const float* __restrict__ xc,
                             const float* __restrict__ xdbl, const float* __restrict__ Alog,
                             float* __restrict__ pr, float* __restrict__ sa)
{
    __shared__ float Bsh[CLK][DS];
    int b = blockIdx.z, c = blockIdx.y;
    int d = blockIdx.x * 256 + threadIdx.x;
    int l0 = c * CLK;
    {
        int l = threadIdx.x >> 2, q = threadIdx.x & 3;
        float4 v = *(const float4*)(xdbl + (size_t)(b * Lseq + l0 + l) * XD + 48 + q * 4);
        Bsh[l][q * 4 + 0] = v.x; Bsh[l][q * 4 + 1] = v.y;
        Bsh[l][q * 4 + 2] = v.z; Bsh[l][q * 4 + 3] = v.w;
    }
    __syncthreads();
    float Ar[DS];
#pragma unroll
    for (int n = 0; n < DS; n++) Ar[n] = -__expf(Alog[(size_t)d * DS + n]);
    float s[DS], p[DS];
#pragma unroll
    for (int n = 0; n < DS; n++) { s[n] = 0.f; p[n] = 1.f; }
    int mbase = b * Lseq + l0;
    for (int l = 0; l < CLK; l++) {
        size_t off = (size_t)(mbase + l) * DI + d;
        float dl = delta[off], u = xc[off];
        float du = dl * u;
#pragma unroll
        for (int n = 0; n < DS; n++) {
            float e = __expf(dl * Ar[n]);
            p[n] *= e;
            s[n] = e * s[n] + du * Bsh[l][n];
        }
    }
    size_t base = ((size_t)(b * NCH + c) * DI + d) * DS;
#pragma unroll
    for (int n = 0; n < DS; n++) { pr[base + n] = p[n]; sa[base + n] = s[n]; }
}

// ---------------- scan phase 2 ----------------
__global__ void scan2_kernel(const float* __restrict__ pr, float* __restrict__ sa)
{
    int gid = blockIdx.x * 256 + threadIdx.x;
    int b = gid / (DI * DS);
    int r = gid - b * (DI * DS);
    float s = 0.f;
    for (int c = 0; c < NCH; c++) {
        size_t idx = (size_t)(b * NCH + c) * (DI * DS) + r;
        float P = pr[idx], Sv = sa[idx];
        sa[idx] = s;
        s = P * s + Sv;
    }
}

// ---------------- scan phase 3 ----------------
__global__ void scan3_kernel(const float* __restrict__ delta, const float* __restrict__ xc,
                             const float* __restrict__ xdbl, const float* __restrict__ Alog,
                             const float* __restrict__ Dv, const float* __restrict__ xz,
                             const float* __restrict__ sa, float* __restrict__ y)
{
    __shared__ float Bsh[CLK][DS];
    __shared__ float Csh[CLK][DS];
    int b = blockIdx.z, c = blockIdx.y;
    int d = blockIdx.x * 256 + threadIdx.x;
    int l0 = c * CLK;
    {
        int l = threadIdx.x >> 2, q = threadIdx.x & 3;
        const float* row = xdbl + (size_t)(b * Lseq + l0 + l) * XD;
        float4 v = *(const float4*)(row + 48 + q * 4);
        float4 u = *(const float4*)(row + 64 + q * 4);
        Bsh[l][q * 4 + 0] = v.x; Bsh[l][q * 4 + 1] = v.y;
        Bsh[l][q * 4 + 2] = v.z; Bsh[l][q * 4 + 3] = v.w;
        Csh[l][q * 4 + 0] = u.x; Csh[l][q * 4 + 1] = u.y;
        Csh[l][q * 4 + 2] = u.z; Csh[l][q * 4 + 3] = u.w;
    }
    __syncthreads();
    float Ar[DS];
#pragma unroll
    for (int n = 0; n < DS; n++) Ar[n] = -__expf(Alog[(size_t)d * DS + n]);
    float s[DS];
    size_t sbase = ((size_t)(b * NCH + c) * DI + d) * DS;
#pragma unroll
    for (int n = 0; n < DS; n++) s[n] = sa[sbase + n];
    float Dval = Dv[d];
    int mbase = b * Lseq + l0;
    for (int l = 0; l < CLK; l++) {
        size_t off = (size_t)(mbase + l) * DI + d;
        float dl = delta[off], u = xc[off];
        float du = dl * u;
        float accv = 0.f;
#pragma unroll
        for (int n = 0; n < DS; n++) {
            float e = __expf(dl * Ar[n]);
            s[n] = e * s[n] + du * Bsh[l][n];
            accv += s[n] * Csh[l][n];
        }
        float z = xz[(size_t)(mbase + l) * (2 * DI) + DI + d];
        float sg = 1.f / (1.f + __expf(-z));
        y[off] = (accv + Dval * u) * (z * sg);
    }
}

// ---------------- launch ----------------
extern "C" void kernel_launch(void* const* d_in, const int* in_sizes, int n_in,
                              void* d_out, int out_size)
{
    (void)in_sizes; (void)n_in; (void)out_size;
    const float* x    = (const float*)d_in[0];
    const float* eW   = (const float*)d_in[1];
    const float* eb   = (const float*)d_in[2];
    const float* nw   = (const float*)d_in[3];
    const float* nb   = (const float*)d_in[4];
    const float* inW  = (const float*)d_in[5];
    const float* cw   = (const float*)d_in[6];
    const float* cb   = (const float*)d_in[7];
    const float* xpW  = (const float*)d_in[8];
    const float* dtW  = (const float*)d_in[9];
    const float* dtb  = (const float*)d_in[10];
    const float* Alog = (const float*)d_in[11];
    const float* Dvec = (const float*)d_in[12];
    const float* outW = (const float*)d_in[13];
    const float* nfw  = (const float*)d_in[14];
    const float* nfb  = (const float*)d_in[15];
    float* outp = (float*)d_out;

    float* buf = nullptr;
    cudaGetSymbolAddress((void**)&buf, g_buf);
    float* h     = buf + OFF_H;
    float* res   = buf + OFF_RES;
    float* hn    = buf + OFF_HN;
    float* xz    = buf + OFF_XZ;
    float* xc    = buf + OFF_XC;
    float* xdbl  = buf + OFF_XDBL;
    float* dlt   = buf + OFF_DELTA;
    float* yb    = buf + OFF_Y;
    float* prb   = buf + OFF_PR;
    float* sab   = buf + OFF_SA;

    embed_kernel<<<Mrows, 256>>>(x, eW, eb, h);

    for (int i = 0; i < NL; i++) {
        ln_kernel<<<Mrows, 256>>>(h, res, nw + (size_t)i * DM, nb + (size_t)i * DM, hn, i == 0 ? 0 : 1);

        // in_proj (tensor cores): [8192,768] x [3072,768]^T -> xz [8192,3072]
        gemm_tn_tc<<<dim3(24, 64), 256>>>(hn, DM, inW + (size_t)i * 2 * DI * DM, DM,
                                          xz, 2 * DI, DM);

        conv_kernel<<<dim3(6, Mrows), 256>>>(xz, cw + (size_t)i * DI * 4, cb + (size_t)i * DI, xc);

        // x_proj (SIMT, N=80 tail): [8192,1536] x [80,1536]^T -> xdbl [8192,80]
        gemm_tn<<<dim3(1, 64), 256>>>(xc, DI, xpW + (size_t)i * XD * DI, DI,
                                      xdbl, XD, XD, DI, nullptr, 0);

        // dt_proj + softplus (SIMT, K=48): [8192,48] x [1536,48]^T -> delta
        gemm_tn<<<dim3(12, 64), 256>>>(xdbl, XD, dtW + (size_t)i * DI * DR, DR,
                                       dlt, DI, DI, DR, dtb + (size_t)i * DI, 1);

        scan1_kernel<<<dim3(6, NCH, Bsz), 256>>>(dlt, xc, xdbl, Alog + (size_t)i * DI * DS, prb, sab);
        scan2_kernel<<<192, 256>>>(prb, sab);
        scan3_kernel<<<dim3(6, NCH, Bsz), 256>>>(dlt, xc, xdbl, Alog + (size_t)i * DI * DS,
                                                 Dvec + (size_t)i * DI, xz, sab, yb);

        // out_proj (tensor cores): [8192,1536] x [768,1536]^T -> h [8192,768]
        gemm_tn_tc<<<dim3(6, 64), 256>>>(yb, DI, outW + (size_t)i * DM * DI, DI,
                                         h, DM, DI);
    }

    ln_kernel<<<Mrows, 256>>>(h, res, nfw, nfb, outp, 1);
}